// round 3
// baseline (speedup 1.0000x reference)
#include <cuda_runtime.h>
#include <math.h>

// TropicalHashGrid: 16-level hash-grid encoding, N=2^21 points, F=2 feats/level.
// Levels 0-4 dense (res^3 <= 2^19), levels 5-15 spatially hashed.

#define L_LEVELS   16
#define HASHMAP_SZ (1u << 19)
#define HASH_MASK  (HASHMAP_SZ - 1u)
#define PRIME_Y    2654435761u
#define PRIME_Z    805459861u
#define NUM_DENSE  5
#define BLOCK_T    128

struct LevelParams {
    float scale[L_LEVELS];
    int   res[L_LEVELS];
};

// Gather 8 corners + trilinear blend. Indices precomputed by caller.
__device__ __forceinline__ float2 blend8(
    const float2* __restrict__ tbl,
    unsigned i000, unsigned i001, unsigned i010, unsigned i011,
    unsigned i100, unsigned i101, unsigned i110, unsigned i111,
    float fx, float fy, float fz)
{
    // Issue all 8 gathers first (MLP=8 per thread-level).
    float2 f000 = __ldg(tbl + i000);
    float2 f001 = __ldg(tbl + i001);
    float2 f010 = __ldg(tbl + i010);
    float2 f011 = __ldg(tbl + i011);
    float2 f100 = __ldg(tbl + i100);
    float2 f101 = __ldg(tbl + i101);
    float2 f110 = __ldg(tbl + i110);
    float2 f111 = __ldg(tbl + i111);

    float wx1 = fx, wx0 = 1.0f - fx;
    float wy1 = fy, wy0 = 1.0f - fy;
    float wz1 = fz, wz0 = 1.0f - fz;
    // (wx*wy)*wz matches reference dim-ordered product.
    float wxy00 = wx0 * wy0, wxy01 = wx0 * wy1;
    float wxy10 = wx1 * wy0, wxy11 = wx1 * wy1;
    float w000 = wxy00 * wz0, w001 = wxy00 * wz1;
    float w010 = wxy01 * wz0, w011 = wxy01 * wz1;
    float w100 = wxy10 * wz0, w101 = wxy10 * wz1;
    float w110 = wxy11 * wz0, w111 = wxy11 * wz1;

    float r0 = w000 * f000.x;
    float r1 = w000 * f000.y;
    r0 = fmaf(w001, f001.x, r0); r1 = fmaf(w001, f001.y, r1);
    r0 = fmaf(w010, f010.x, r0); r1 = fmaf(w010, f010.y, r1);
    r0 = fmaf(w011, f011.x, r0); r1 = fmaf(w011, f011.y, r1);
    r0 = fmaf(w100, f100.x, r0); r1 = fmaf(w100, f100.y, r1);
    r0 = fmaf(w101, f101.x, r0); r1 = fmaf(w101, f101.y, r1);
    r0 = fmaf(w110, f110.x, r0); r1 = fmaf(w110, f110.y, r1);
    r0 = fmaf(w111, f111.x, r0); r1 = fmaf(w111, f111.y, r1);
    return make_float2(r0, r1);
}

__global__ void __launch_bounds__(BLOCK_T)
hashgrid_kernel(const float* __restrict__ xs,
                const float* __restrict__ table,
                float* __restrict__ out,
                int n, LevelParams lp)
{
    // Padded staging buffer: stride 33 floats -> conflict-free column writes
    // and conflict-free row reads during the coalesced copy-out.
    __shared__ float sbuf[BLOCK_T * 33];

    const int tid = threadIdx.x;
    const int p0  = blockIdx.x * BLOCK_T;
    const int pt  = p0 + tid;
    const int ptc = (pt < n) ? pt : (n - 1);   // clamp; copy-out guards validity

    const float px = xs[(size_t)ptc * 3 + 0];
    const float py = xs[(size_t)ptc * 3 + 1];
    const float pz = xs[(size_t)ptc * 3 + 2];

    // ---- Dense levels 0..4: flat = x + y*res + z*res^2, clamped to res-1 ----
    #pragma unroll 1
    for (int l = 0; l < NUM_DENSE; ++l) {
        const float2* __restrict__ tbl =
            reinterpret_cast<const float2*>(table) + (size_t)l * HASHMAP_SZ;
        const float scale = lp.scale[l];
        const int   res   = lp.res[l];

        // Unfused mul+add to match reference elementwise x*scale + 0.5.
        const float posx = __fadd_rn(__fmul_rn(px, scale), 0.5f);
        const float posy = __fadd_rn(__fmul_rn(py, scale), 0.5f);
        const float posz = __fadd_rn(__fmul_rn(pz, scale), 0.5f);
        const float pfx = floorf(posx), pfy = floorf(posy), pfz = floorf(posz);
        const float fx = posx - pfx, fy = posy - pfy, fz = posz - pfz;
        const int gx = (int)pfx, gy = (int)pfy, gz = (int)pfz;

        const int r1 = res - 1;
        const int r2 = res * res;
        const int x0 = min(gx,     r1), x1 = min(gx + 1, r1);
        const int y0 = min(gy,     r1) * res, y1 = min(gy + 1, r1) * res;
        const int z0 = min(gz,     r1) * r2,  z1 = min(gz + 1, r1) * r2;

        float2 r = blend8(tbl,
            (unsigned)(x0 + y0 + z0), (unsigned)(x0 + y0 + z1),
            (unsigned)(x0 + y1 + z0), (unsigned)(x0 + y1 + z1),
            (unsigned)(x1 + y0 + z0), (unsigned)(x1 + y0 + z1),
            (unsigned)(x1 + y1 + z0), (unsigned)(x1 + y1 + z1),
            fx, fy, fz);

        sbuf[tid * 33 + 2 * l + 0] = r.x;
        sbuf[tid * 33 + 2 * l + 1] = r.y;
    }

    // ---- Hash levels 5..15: (x*1) ^ (y*P1) ^ (z*P2) & mask ----
    #pragma unroll 1
    for (int l = NUM_DENSE; l < L_LEVELS; ++l) {
        const float2* __restrict__ tbl =
            reinterpret_cast<const float2*>(table) + (size_t)l * HASHMAP_SZ;
        const float scale = lp.scale[l];

        const float posx = __fadd_rn(__fmul_rn(px, scale), 0.5f);
        const float posy = __fadd_rn(__fmul_rn(py, scale), 0.5f);
        const float posz = __fadd_rn(__fmul_rn(pz, scale), 0.5f);
        const float pfx = floorf(posx), pfy = floorf(posy), pfz = floorf(posz);
        const float fx = posx - pfx, fy = posy - pfy, fz = posz - pfz;

        const unsigned hx0 = (unsigned)(int)pfx;
        const unsigned hx1 = hx0 + 1u;
        const unsigned hy0 = (unsigned)(int)pfy * PRIME_Y;
        const unsigned hy1 = hy0 + PRIME_Y;          // (y+1)*P1 mod 2^32
        const unsigned hz0 = (unsigned)(int)pfz * PRIME_Z;
        const unsigned hz1 = hz0 + PRIME_Z;

        float2 r = blend8(tbl,
            (hx0 ^ hy0 ^ hz0) & HASH_MASK, (hx0 ^ hy0 ^ hz1) & HASH_MASK,
            (hx0 ^ hy1 ^ hz0) & HASH_MASK, (hx0 ^ hy1 ^ hz1) & HASH_MASK,
            (hx1 ^ hy0 ^ hz0) & HASH_MASK, (hx1 ^ hy0 ^ hz1) & HASH_MASK,
            (hx1 ^ hy1 ^ hz0) & HASH_MASK, (hx1 ^ hy1 ^ hz1) & HASH_MASK,
            fx, fy, fz);

        sbuf[tid * 33 + 2 * l + 0] = r.x;
        sbuf[tid * 33 + 2 * l + 1] = r.y;
    }

    __syncthreads();

    // Coalesced copy-out: out[(p0+pl)*32 + c]. Streaming stores keep the
    // 256MB output from evicting the 64MB of hash tables out of L2.
    const int nvalid = min(BLOCK_T, n - p0);
    float* __restrict__ ob = out + (size_t)p0 * 32;
    const int total = nvalid * 32;
    #pragma unroll 4
    for (int k = tid; k < total; k += BLOCK_T) {
        __stcs(ob + k, sbuf[(k >> 5) * 33 + (k & 31)]);
    }
}

extern "C" void kernel_launch(void* const* d_in, const int* in_sizes, int n_in,
                              void* d_out, int out_size)
{
    const int n = out_size / (L_LEVELS * 2);   // out is [N, 32] float32

    // Identify inputs by size: x has n*3 elements, table has 16*2^19*2.
    const float* x   = (const float*)d_in[0];
    const float* tbl = (const float*)d_in[1];
    if (n_in >= 2 && in_sizes[0] != n * 3) {
        x   = (const float*)d_in[1];
        tbl = (const float*)d_in[0];
    }

    // Level scales in double, same pow(B, l) form as the reference.
    LevelParams lp;
    const double B = pow(2.0, 7.0 / 15.0);     // log2(2048/16)/15
    for (int l = 0; l < L_LEVELS; ++l) {
        const double s = 16.0 * pow(B, (double)l) - 1.0;
        lp.scale[l] = (float)s;
        lp.res[l]   = (int)ceil(s) + 1;
    }

    const int grid = (n + BLOCK_T - 1) / BLOCK_T;
    hashgrid_kernel<<<grid, BLOCK_T>>>(x, tbl, (float*)d_out, n, lp);
}

// round 4
// speedup vs baseline: 1.2854x; 1.2854x over previous
#include <cuda_runtime.h>
#include <math.h>

// TropicalHashGrid: 16-level hash-grid encoding, N=2^21 points, F=2 feats/level.
// Levels 0-4 dense (res^3 <= 2^19), levels 5-15 spatially hashed.
//
// R3 changes vs R2 (1779us, L1=47.7%, issue=9.6%, regs=32):
//  - paired LDG.128 for x-corner pairs on even hx (PRIME_x==1 => indices a, a^1)
//  - __launch_bounds__(128, 8): allow 64 regs so 2 levels of gathers stay in flight
//  - #pragma unroll 2 on the hash loop for ~16 outstanding gathers/thread

#define L_LEVELS   16
#define HASHMAP_SZ (1u << 19)
#define HASH_MASK  (HASHMAP_SZ - 1u)
#define PRIME_Y    2654435761u
#define PRIME_Z    805459861u
#define NUM_DENSE  5
#define BLOCK_T    128

struct LevelParams {
    float scale[L_LEVELS];
    int   res[L_LEVELS];
};

__device__ __forceinline__ float2 pick_half(const float4 q, unsigned idx) {
    // float4 at pair (idx>>1) covers float2 entries {idx&~1, idx|1}
    return (idx & 1u) ? make_float2(q.z, q.w) : make_float2(q.x, q.y);
}

// Trilinear blend of 8 corner features. f[j] = x0 corner with yz combo j,
// f[4+j] = x1 corner with yz combo j, j in {00,01,10,11} (z fastest).
__device__ __forceinline__ float2 blend8v(const float2* f,
                                          float fx, float fy, float fz)
{
    float wx1 = fx, wx0 = 1.0f - fx;
    float wy1 = fy, wy0 = 1.0f - fy;
    float wz1 = fz, wz0 = 1.0f - fz;
    float wxy00 = wx0 * wy0, wxy01 = wx0 * wy1;
    float wxy10 = wx1 * wy0, wxy11 = wx1 * wy1;
    float w[8];
    w[0] = wxy00 * wz0; w[1] = wxy00 * wz1;
    w[2] = wxy01 * wz0; w[3] = wxy01 * wz1;
    w[4] = wxy10 * wz0; w[5] = wxy10 * wz1;
    w[6] = wxy11 * wz0; w[7] = wxy11 * wz1;

    float r0 = w[0] * f[0].x;
    float r1 = w[0] * f[0].y;
    #pragma unroll
    for (int j = 1; j < 8; ++j) {
        r0 = fmaf(w[j], f[j].x, r0);
        r1 = fmaf(w[j], f[j].y, r1);
    }
    return make_float2(r0, r1);
}

__global__ void __launch_bounds__(BLOCK_T, 8)
hashgrid_kernel(const float* __restrict__ xs,
                const float* __restrict__ table,
                float* __restrict__ out,
                int n, LevelParams lp)
{
    // Padded staging buffer: stride 33 floats -> conflict-free column writes
    // and conflict-free row reads during the coalesced copy-out.
    __shared__ float sbuf[BLOCK_T * 33];

    const int tid = threadIdx.x;
    const int p0  = blockIdx.x * BLOCK_T;
    const int pt  = p0 + tid;
    const int ptc = (pt < n) ? pt : (n - 1);   // clamp; copy-out guards validity

    const float px = xs[(size_t)ptc * 3 + 0];
    const float py = xs[(size_t)ptc * 3 + 1];
    const float pz = xs[(size_t)ptc * 3 + 2];

    // ---- Dense levels 0..4: flat = x + y*res + z*res^2, clamped to res-1 ----
    #pragma unroll 1
    for (int l = 0; l < NUM_DENSE; ++l) {
        const float2* __restrict__ tbl =
            reinterpret_cast<const float2*>(table) + (size_t)l * HASHMAP_SZ;
        const float scale = lp.scale[l];
        const int   res   = lp.res[l];

        // Unfused mul+add to match reference elementwise x*scale + 0.5.
        const float posx = __fadd_rn(__fmul_rn(px, scale), 0.5f);
        const float posy = __fadd_rn(__fmul_rn(py, scale), 0.5f);
        const float posz = __fadd_rn(__fmul_rn(pz, scale), 0.5f);
        const float pfx = floorf(posx), pfy = floorf(posy), pfz = floorf(posz);
        const float fx = posx - pfx, fy = posy - pfy, fz = posz - pfz;
        const int gx = (int)pfx, gy = (int)pfy, gz = (int)pfz;

        const int r1 = res - 1;
        const int r2 = res * res;
        const int x0 = min(gx,     r1), x1 = min(gx + 1, r1);
        const int y0 = min(gy,     r1) * res, y1 = min(gy + 1, r1) * res;
        const int z0 = min(gz,     r1) * r2,  z1 = min(gz + 1, r1) * r2;

        float2 f[8];
        f[0] = __ldg(tbl + (x0 + y0 + z0));
        f[1] = __ldg(tbl + (x0 + y0 + z1));
        f[2] = __ldg(tbl + (x0 + y1 + z0));
        f[3] = __ldg(tbl + (x0 + y1 + z1));
        f[4] = __ldg(tbl + (x1 + y0 + z0));
        f[5] = __ldg(tbl + (x1 + y0 + z1));
        f[6] = __ldg(tbl + (x1 + y1 + z0));
        f[7] = __ldg(tbl + (x1 + y1 + z1));

        float2 r = blend8v(f, fx, fy, fz);
        sbuf[tid * 33 + 2 * l + 0] = r.x;
        sbuf[tid * 33 + 2 * l + 1] = r.y;
    }

    // ---- Hash levels 5..15: (x*1) ^ (y*P1) ^ (z*P2) & mask ----
    // PRIME_x == 1 => when hx0 is even, the x0/x1 corners for a fixed (y,z)
    // are table entries a and a^1: one aligned LDG.128 serves both.
    #pragma unroll 2
    for (int l = NUM_DENSE; l < L_LEVELS; ++l) {
        const float2* __restrict__ tbl =
            reinterpret_cast<const float2*>(table) + (size_t)l * HASHMAP_SZ;
        const float scale = lp.scale[l];

        const float posx = __fadd_rn(__fmul_rn(px, scale), 0.5f);
        const float posy = __fadd_rn(__fmul_rn(py, scale), 0.5f);
        const float posz = __fadd_rn(__fmul_rn(pz, scale), 0.5f);
        const float pfx = floorf(posx), pfy = floorf(posy), pfz = floorf(posz);
        const float fx = posx - pfx, fy = posy - pfy, fz = posz - pfz;

        const unsigned hx0 = (unsigned)(int)pfx;
        const unsigned hx1 = hx0 + 1u;
        const unsigned hy0 = (unsigned)(int)pfy * PRIME_Y;
        const unsigned hy1 = hy0 + PRIME_Y;          // (y+1)*P1 mod 2^32
        const unsigned hz0 = (unsigned)(int)pfz * PRIME_Z;
        const unsigned hz1 = hz0 + PRIME_Z;

        const unsigned hyz0 = hy0 ^ hz0;
        const unsigned hyz1 = hy0 ^ hz1;
        const unsigned hyz2 = hy1 ^ hz0;
        const unsigned hyz3 = hy1 ^ hz1;

        float2 f[8];
        if ((hx0 & 1u) == 0u) {
            // Paired path: 4 x LDG.128 fetches both x-corners per (y,z).
            const float4* __restrict__ t4 =
                reinterpret_cast<const float4*>(tbl);
            const unsigned a0 = (hx0 ^ hyz0) & HASH_MASK;
            const unsigned a1 = (hx0 ^ hyz1) & HASH_MASK;
            const unsigned a2 = (hx0 ^ hyz2) & HASH_MASK;
            const unsigned a3 = (hx0 ^ hyz3) & HASH_MASK;
            const float4 q0 = __ldg(t4 + (a0 >> 1));
            const float4 q1 = __ldg(t4 + (a1 >> 1));
            const float4 q2 = __ldg(t4 + (a2 >> 1));
            const float4 q3 = __ldg(t4 + (a3 >> 1));
            f[0] = pick_half(q0, a0); f[4] = pick_half(q0, a0 ^ 1u);
            f[1] = pick_half(q1, a1); f[5] = pick_half(q1, a1 ^ 1u);
            f[2] = pick_half(q2, a2); f[6] = pick_half(q2, a2 ^ 1u);
            f[3] = pick_half(q3, a3); f[7] = pick_half(q3, a3 ^ 1u);
        } else {
            f[0] = __ldg(tbl + ((hx0 ^ hyz0) & HASH_MASK));
            f[1] = __ldg(tbl + ((hx0 ^ hyz1) & HASH_MASK));
            f[2] = __ldg(tbl + ((hx0 ^ hyz2) & HASH_MASK));
            f[3] = __ldg(tbl + ((hx0 ^ hyz3) & HASH_MASK));
            f[4] = __ldg(tbl + ((hx1 ^ hyz0) & HASH_MASK));
            f[5] = __ldg(tbl + ((hx1 ^ hyz1) & HASH_MASK));
            f[6] = __ldg(tbl + ((hx1 ^ hyz2) & HASH_MASK));
            f[7] = __ldg(tbl + ((hx1 ^ hyz3) & HASH_MASK));
        }

        float2 r = blend8v(f, fx, fy, fz);
        sbuf[tid * 33 + 2 * l + 0] = r.x;
        sbuf[tid * 33 + 2 * l + 1] = r.y;
    }

    __syncthreads();

    // Coalesced copy-out: out[(p0+pl)*32 + c]. Streaming stores keep the
    // 256MB output from evicting the 64MB of hash tables out of L2.
    const int nvalid = min(BLOCK_T, n - p0);
    float* __restrict__ ob = out + (size_t)p0 * 32;
    const int total = nvalid * 32;
    #pragma unroll 4
    for (int k = tid; k < total; k += BLOCK_T) {
        __stcs(ob + k, sbuf[(k >> 5) * 33 + (k & 31)]);
    }
}

extern "C" void kernel_launch(void* const* d_in, const int* in_sizes, int n_in,
                              void* d_out, int out_size)
{
    const int n = out_size / (L_LEVELS * 2);   // out is [N, 32] float32

    // Identify inputs by size: x has n*3 elements, table has 16*2^19*2.
    const float* x   = (const float*)d_in[0];
    const float* tbl = (const float*)d_in[1];
    if (n_in >= 2 && in_sizes[0] != n * 3) {
        x   = (const float*)d_in[1];
        tbl = (const float*)d_in[0];
    }

    // Level scales in double, same pow(B, l) form as the reference.
    LevelParams lp;
    const double B = pow(2.0, 7.0 / 15.0);     // log2(2048/16)/15
    for (int l = 0; l < L_LEVELS; ++l) {
        const double s = 16.0 * pow(B, (double)l) - 1.0;
        lp.scale[l] = (float)s;
        lp.res[l]   = (int)ceil(s) + 1;
    }

    const int grid = (n + BLOCK_T - 1) / BLOCK_T;
    hashgrid_kernel<<<grid, BLOCK_T>>>(x, tbl, (float*)d_out, n, lp);
}

// round 5
// speedup vs baseline: 1.5395x; 1.1977x over previous
#include <cuda_runtime.h>
#include <math.h>

// TropicalHashGrid: 16-level hash-grid encoding, N=2^21 points, F=2 feats/level.
// Levels 0-4 dense (res^3 <= 2^19), levels 5-15 spatially hashed.
//
// R5 changes vs R4 (1384us; l1tex replay-bound at ~109 wavefronts/point):
//  - prologue kernel builds a duplicated-pair dense table (float4 = x0,x1
//    corners) => dense gathers 40 -> 20 wavefronts/point
//  - coordinates staged through SMEM with coalesced LDG.128
//  - hash levels keep the PRIME_x==1 even-pairing (E[6] wf/level)

#define L_LEVELS   16
#define HASHMAP_SZ (1u << 19)
#define HASH_MASK  (HASHMAP_SZ - 1u)
#define PRIME_Y    2654435761u
#define PRIME_Z    805459861u
#define NUM_DENSE  5
#define BLOCK_T    128

// Dense dup-table scratch: res = {16,23,31,43,59} -> 330,940 entries total.
#define DENSE_TOTAL_MAX 340000
__device__ float4 g_dense[DENSE_TOTAL_MAX];   // ~5.4 MB, 16B-aligned

struct LevelParams {
    float scale[L_LEVELS];
    int   res[L_LEVELS];
    int   doff[NUM_DENSE];   // per-level entry offset into g_dense
};

// ---------------- prologue: build duplicated-pair dense table ----------------
__global__ void build_dense_kernel(const float* __restrict__ table,
                                   LevelParams lp, int total)
{
    int i = blockIdx.x * blockDim.x + threadIdx.x;
    if (i >= total) return;
    int l = 0;
    #pragma unroll
    for (int k = 1; k < NUM_DENSE; ++k) if (i >= lp.doff[k]) l = k;
    const int flat = i - lp.doff[l];
    const int res  = lp.res[l];
    const int r2   = res * res;
    const int z    = flat / r2;
    const int rem  = flat - z * r2;
    const int y    = rem / res;
    const int x    = rem - y * res;
    const float2* __restrict__ tbl =
        reinterpret_cast<const float2*>(table) + (size_t)l * HASHMAP_SZ;
    const float2 a = tbl[flat];
    const int   x1 = min(x + 1, res - 1);
    const float2 b = tbl[x1 + y * res + z * r2];
    g_dense[i] = make_float4(a.x, a.y, b.x, b.y);
}

// ---------------- helpers ----------------
__device__ __forceinline__ float2 pick_half(const float4 q, unsigned idx) {
    return (idx & 1u) ? make_float2(q.z, q.w) : make_float2(q.x, q.y);
}

// Trilinear blend. f[j] = x0 corner, f[4+j] = x1 corner, j = (y,z) combo
// with z fastest: {00,01,10,11}. Matches reference dim-ordered product.
__device__ __forceinline__ float2 blend8v(const float2* f,
                                          float fx, float fy, float fz)
{
    float wx1 = fx, wx0 = 1.0f - fx;
    float wy1 = fy, wy0 = 1.0f - fy;
    float wz1 = fz, wz0 = 1.0f - fz;
    float wxy00 = wx0 * wy0, wxy01 = wx0 * wy1;
    float wxy10 = wx1 * wy0, wxy11 = wx1 * wy1;
    float w[8];
    w[0] = wxy00 * wz0; w[1] = wxy00 * wz1;
    w[2] = wxy01 * wz0; w[3] = wxy01 * wz1;
    w[4] = wxy10 * wz0; w[5] = wxy10 * wz1;
    w[6] = wxy11 * wz0; w[7] = wxy11 * wz1;

    float r0 = w[0] * f[0].x;
    float r1 = w[0] * f[0].y;
    #pragma unroll
    for (int j = 1; j < 8; ++j) {
        r0 = fmaf(w[j], f[j].x, r0);
        r1 = fmaf(w[j], f[j].y, r1);
    }
    return make_float2(r0, r1);
}

// ---------------- main kernel ----------------
__global__ void __launch_bounds__(BLOCK_T, 8)
hashgrid_kernel(const float* __restrict__ xs,
                const float* __restrict__ table,
                float* __restrict__ out,
                int n, LevelParams lp)
{
    // Staging buffer. Used twice:
    //  1) coalesced coordinate load (384 floats per block)
    //  2) per-point results, stride 33 -> conflict-free writes and reads
    __shared__ float sbuf[BLOCK_T * 33];

    const int tid = threadIdx.x;
    const int p0  = blockIdx.x * BLOCK_T;
    const int pt  = p0 + tid;

    float px, py, pz;
    if (p0 + BLOCK_T <= n) {
        // Coalesced: 96 lanes each fetch one float4 (3*128 floats total).
        if (tid < 96) {
            const float4 v = __ldg(reinterpret_cast<const float4*>(
                                       xs + (size_t)p0 * 3) + tid);
            reinterpret_cast<float4*>(sbuf)[tid] = v;
        }
        __syncthreads();
        px = sbuf[tid * 3 + 0];
        py = sbuf[tid * 3 + 1];
        pz = sbuf[tid * 3 + 2];
        __syncthreads();   // sbuf reused for outputs below
    } else {
        const int ptc = (pt < n) ? pt : (n - 1);
        px = xs[(size_t)ptc * 3 + 0];
        py = xs[(size_t)ptc * 3 + 1];
        pz = xs[(size_t)ptc * 3 + 2];
    }

    // ---- Dense levels 0..4 via duplicated-pair table: 4 x LDG.128 each ----
    #pragma unroll 1
    for (int l = 0; l < NUM_DENSE; ++l) {
        const float4* __restrict__ dtab = g_dense + lp.doff[l];
        const float scale = lp.scale[l];
        const int   res   = lp.res[l];

        // Unfused mul+add to match reference elementwise x*scale + 0.5.
        const float posx = __fadd_rn(__fmul_rn(px, scale), 0.5f);
        const float posy = __fadd_rn(__fmul_rn(py, scale), 0.5f);
        const float posz = __fadd_rn(__fmul_rn(pz, scale), 0.5f);
        const float pfx = floorf(posx), pfy = floorf(posy), pfz = floorf(posz);
        const float fx = posx - pfx, fy = posy - pfy, fz = posz - pfz;
        const int gx = (int)pfx, gy = (int)pfy, gz = (int)pfz;

        const int r1 = res - 1;
        const int r2 = res * res;
        // gx <= res-1 always (pos < scale+0.5 <= res-0.5); x1 clamp is baked
        // into the dup table.
        const int y0 = min(gy,     r1) * res, y1 = min(gy + 1, r1) * res;
        const int z0 = min(gz,     r1) * r2,  z1 = min(gz + 1, r1) * r2;

        const float4 q0 = __ldg(dtab + (gx + y0 + z0));
        const float4 q1 = __ldg(dtab + (gx + y0 + z1));
        const float4 q2 = __ldg(dtab + (gx + y1 + z0));
        const float4 q3 = __ldg(dtab + (gx + y1 + z1));

        float2 f[8];
        f[0] = make_float2(q0.x, q0.y); f[4] = make_float2(q0.z, q0.w);
        f[1] = make_float2(q1.x, q1.y); f[5] = make_float2(q1.z, q1.w);
        f[2] = make_float2(q2.x, q2.y); f[6] = make_float2(q2.z, q2.w);
        f[3] = make_float2(q3.x, q3.y); f[7] = make_float2(q3.z, q3.w);

        float2 r = blend8v(f, fx, fy, fz);
        sbuf[tid * 33 + 2 * l + 0] = r.x;
        sbuf[tid * 33 + 2 * l + 1] = r.y;
    }

    // ---- Hash levels 5..15: (x*1) ^ (y*P1) ^ (z*P2) & mask ----
    // PRIME_x == 1 => when hx0 is even, x0/x1 corners for fixed (y,z) are
    // adjacent table entries: one aligned LDG.128 serves both.
    #pragma unroll 2
    for (int l = NUM_DENSE; l < L_LEVELS; ++l) {
        const float2* __restrict__ tbl =
            reinterpret_cast<const float2*>(table) + (size_t)l * HASHMAP_SZ;
        const float scale = lp.scale[l];

        const float posx = __fadd_rn(__fmul_rn(px, scale), 0.5f);
        const float posy = __fadd_rn(__fmul_rn(py, scale), 0.5f);
        const float posz = __fadd_rn(__fmul_rn(pz, scale), 0.5f);
        const float pfx = floorf(posx), pfy = floorf(posy), pfz = floorf(posz);
        const float fx = posx - pfx, fy = posy - pfy, fz = posz - pfz;

        const unsigned hx0 = (unsigned)(int)pfx;
        const unsigned hx1 = hx0 + 1u;
        const unsigned hy0 = (unsigned)(int)pfy * PRIME_Y;
        const unsigned hy1 = hy0 + PRIME_Y;          // (y+1)*P1 mod 2^32
        const unsigned hz0 = (unsigned)(int)pfz * PRIME_Z;
        const unsigned hz1 = hz0 + PRIME_Z;

        const unsigned hyz0 = hy0 ^ hz0;
        const unsigned hyz1 = hy0 ^ hz1;
        const unsigned hyz2 = hy1 ^ hz0;
        const unsigned hyz3 = hy1 ^ hz1;

        float2 f[8];
        if ((hx0 & 1u) == 0u) {
            const float4* __restrict__ t4 =
                reinterpret_cast<const float4*>(tbl);
            const unsigned a0 = (hx0 ^ hyz0) & HASH_MASK;
            const unsigned a1 = (hx0 ^ hyz1) & HASH_MASK;
            const unsigned a2 = (hx0 ^ hyz2) & HASH_MASK;
            const unsigned a3 = (hx0 ^ hyz3) & HASH_MASK;
            const float4 q0 = __ldg(t4 + (a0 >> 1));
            const float4 q1 = __ldg(t4 + (a1 >> 1));
            const float4 q2 = __ldg(t4 + (a2 >> 1));
            const float4 q3 = __ldg(t4 + (a3 >> 1));
            f[0] = pick_half(q0, a0); f[4] = pick_half(q0, a0 ^ 1u);
            f[1] = pick_half(q1, a1); f[5] = pick_half(q1, a1 ^ 1u);
            f[2] = pick_half(q2, a2); f[6] = pick_half(q2, a2 ^ 1u);
            f[3] = pick_half(q3, a3); f[7] = pick_half(q3, a3 ^ 1u);
        } else {
            f[0] = __ldg(tbl + ((hx0 ^ hyz0) & HASH_MASK));
            f[1] = __ldg(tbl + ((hx0 ^ hyz1) & HASH_MASK));
            f[2] = __ldg(tbl + ((hx0 ^ hyz2) & HASH_MASK));
            f[3] = __ldg(tbl + ((hx0 ^ hyz3) & HASH_MASK));
            f[4] = __ldg(tbl + ((hx1 ^ hyz0) & HASH_MASK));
            f[5] = __ldg(tbl + ((hx1 ^ hyz1) & HASH_MASK));
            f[6] = __ldg(tbl + ((hx1 ^ hyz2) & HASH_MASK));
            f[7] = __ldg(tbl + ((hx1 ^ hyz3) & HASH_MASK));
        }

        float2 r = blend8v(f, fx, fy, fz);
        sbuf[tid * 33 + 2 * l + 0] = r.x;
        sbuf[tid * 33 + 2 * l + 1] = r.y;
    }

    __syncthreads();

    // Coalesced copy-out. Streaming stores keep the 256MB output from
    // evicting the 64MB of hash tables out of L2.
    const int nvalid = min(BLOCK_T, n - p0);
    float* __restrict__ ob = out + (size_t)p0 * 32;
    const int total = nvalid * 32;
    #pragma unroll 4
    for (int k = tid; k < total; k += BLOCK_T) {
        __stcs(ob + k, sbuf[(k >> 5) * 33 + (k & 31)]);
    }
}

extern "C" void kernel_launch(void* const* d_in, const int* in_sizes, int n_in,
                              void* d_out, int out_size)
{
    const int n = out_size / (L_LEVELS * 2);   // out is [N, 32] float32

    // Identify inputs by size: x has n*3 elements, table has 16*2^19*2.
    const float* x   = (const float*)d_in[0];
    const float* tbl = (const float*)d_in[1];
    if (n_in >= 2 && in_sizes[0] != n * 3) {
        x   = (const float*)d_in[1];
        tbl = (const float*)d_in[0];
    }

    // Level scales in double, same pow(B, l) form as the reference.
    LevelParams lp;
    const double B = pow(2.0, 7.0 / 15.0);     // log2(2048/16)/15
    int off = 0;
    for (int l = 0; l < L_LEVELS; ++l) {
        const double s = 16.0 * pow(B, (double)l) - 1.0;
        lp.scale[l] = (float)s;
        lp.res[l]   = (int)ceil(s) + 1;
        if (l < NUM_DENSE) {
            lp.doff[l] = off;
            off += lp.res[l] * lp.res[l] * lp.res[l];
        }
    }
    const int dense_total = off;   // 330,940 for the default config

    // Prologue: build duplicated-pair dense table (same graph, deterministic).
    const int pgrid = (dense_total + 255) / 256;
    build_dense_kernel<<<pgrid, 256>>>(tbl, lp, dense_total);

    const int grid = (n + BLOCK_T - 1) / BLOCK_T;
    hashgrid_kernel<<<grid, BLOCK_T>>>(x, tbl, (float*)d_out, n, lp);
}

// round 7
// speedup vs baseline: 2.0238x; 1.3146x over previous
#include <cuda_runtime.h>
#include <cuda_fp16.h>
#include <math.h>

// TropicalHashGrid: 16-level hash-grid encoding, N=2^21 points, F=2 feats/level.
// Levels 0-4 dense, levels 5-15 spatially hashed.
//
// R7 = R6 with the nonexistent __half2_as_uint/__uint_as_half2 intrinsics
// replaced by reinterpret_cast bit-casts. Changes vs R5 (1156us):
//  - fp16 tables (tcnn-style). Quantization err ~2^-11, well under 1e-3.
//  - dense: 2x2 (x,y)-patch dup table, 16B/entry -> 2 LDG.128 per level (was 4)
//  - hash: fp16 4-entry groups; partner index a^m with m=hx^(hx+1); m<=3
//    (prob 3/4) -> both x-corners in one LDG.128. E[wf] 6 -> 5 per level.

#define L_LEVELS   16
#define HASHMAP_SZ (1u << 19)
#define HASH_MASK  (HASHMAP_SZ - 1u)
#define PRIME_Y    2654435761u
#define PRIME_Z    805459861u
#define NUM_DENSE  5
#define NUM_HASH   (L_LEVELS - NUM_DENSE)
#define BLOCK_T    128

// Scratch (static __device__: allocation-free).
// Dense patch table: res = {16,23,31,43,59} -> 330,940 entries * 16B = 5.3MB
#define DENSE_TOTAL_MAX 340000
__device__ __align__(16) uint4 g_dpatch[DENSE_TOTAL_MAX];
// fp16 hash tables: 11 levels * 2^19 entries * 4B = 23MB
__device__ __align__(16) unsigned g_hash[NUM_HASH * HASHMAP_SZ];

struct LevelParams {
    float scale[L_LEVELS];
    int   res[L_LEVELS];
    int   doff[NUM_DENSE];
};

// ------------- bit-cast helpers -------------
__device__ __forceinline__ unsigned h2_to_u(__half2 h) {
    return *reinterpret_cast<unsigned*>(&h);
}
__device__ __forceinline__ float2 h2f(unsigned u) {
    return __half22float2(*reinterpret_cast<__half2*>(&u));
}

// ------------- prologue 1: fp16 hash tables -------------
__global__ void build_hash_kernel(const float* __restrict__ table)
{
    const int i = blockIdx.x * blockDim.x + threadIdx.x;
    if (i >= NUM_HASH * (int)HASHMAP_SZ) return;
    const int lvl = i >> 19;                 // 0..10 -> level 5..15
    const int idx = i & (int)HASH_MASK;
    const float2 v = reinterpret_cast<const float2*>(table)
                         [(size_t)(lvl + NUM_DENSE) * HASHMAP_SZ + idx];
    g_hash[i] = h2_to_u(__floats2half2_rn(v.x, v.y));
}

// ------------- prologue 2: dense 2x2 patch table -------------
// entry(x,y,z) = { f(x,y,z), f(x1,y,z), f(x,y1,z), f(x1,y1,z) } as 4 half2,
// with x1=min(x+1,r1), y1=min(y+1,r1) clamping baked in.
__global__ void build_dense_kernel(const float* __restrict__ table,
                                   LevelParams lp, int total)
{
    const int i = blockIdx.x * blockDim.x + threadIdx.x;
    if (i >= total) return;
    int l = 0;
    #pragma unroll
    for (int k = 1; k < NUM_DENSE; ++k) if (i >= lp.doff[k]) l = k;
    const int flat = i - lp.doff[l];
    const int res  = lp.res[l];
    const int r2   = res * res;
    const int z    = flat / r2;
    const int rem  = flat - z * r2;
    const int y    = rem / res;
    const int x    = rem - y * res;
    const int x1   = min(x + 1, res - 1);
    const int y1   = min(y + 1, res - 1);
    const float2* __restrict__ tbl =
        reinterpret_cast<const float2*>(table) + (size_t)l * HASHMAP_SZ;
    const float2 c00 = tbl[x  + y  * res + z * r2];
    const float2 c10 = tbl[x1 + y  * res + z * r2];
    const float2 c01 = tbl[x  + y1 * res + z * r2];
    const float2 c11 = tbl[x1 + y1 * res + z * r2];
    uint4 q;
    q.x = h2_to_u(__floats2half2_rn(c00.x, c00.y));
    q.y = h2_to_u(__floats2half2_rn(c10.x, c10.y));
    q.z = h2_to_u(__floats2half2_rn(c01.x, c01.y));
    q.w = h2_to_u(__floats2half2_rn(c11.x, c11.y));
    g_dpatch[i] = q;
}

// ------------- helpers -------------
// Select component j (0..3) of a uint4.
__device__ __forceinline__ unsigned comp4(const uint4 q, unsigned j) {
    const unsigned lo = (j & 1u) ? q.y : q.x;
    const unsigned hi = (j & 1u) ? q.w : q.z;
    return (j & 2u) ? hi : lo;
}

// Trilinear blend. f[j] = x0 corner, f[4+j] = x1 corner, j = (y,z) combo
// with z fastest: {00,01,10,11}. Matches reference dim-ordered product.
__device__ __forceinline__ float2 blend8v(const float2* f,
                                          float fx, float fy, float fz)
{
    float wx1 = fx, wx0 = 1.0f - fx;
    float wy1 = fy, wy0 = 1.0f - fy;
    float wz1 = fz, wz0 = 1.0f - fz;
    float wxy00 = wx0 * wy0, wxy01 = wx0 * wy1;
    float wxy10 = wx1 * wy0, wxy11 = wx1 * wy1;
    float w[8];
    w[0] = wxy00 * wz0; w[1] = wxy00 * wz1;
    w[2] = wxy01 * wz0; w[3] = wxy01 * wz1;
    w[4] = wxy10 * wz0; w[5] = wxy10 * wz1;
    w[6] = wxy11 * wz0; w[7] = wxy11 * wz1;

    float r0 = w[0] * f[0].x;
    float r1 = w[0] * f[0].y;
    #pragma unroll
    for (int j = 1; j < 8; ++j) {
        r0 = fmaf(w[j], f[j].x, r0);
        r1 = fmaf(w[j], f[j].y, r1);
    }
    return make_float2(r0, r1);
}

// ------------- main kernel -------------
__global__ void __launch_bounds__(BLOCK_T, 8)
hashgrid_kernel(const float* __restrict__ xs,
                float* __restrict__ out,
                int n, LevelParams lp)
{
    __shared__ float sbuf[BLOCK_T * 33];   // coords, then results (stride 33)

    const int tid = threadIdx.x;
    const int p0  = blockIdx.x * BLOCK_T;
    const int pt  = p0 + tid;

    float px, py, pz;
    if (p0 + BLOCK_T <= n) {
        if (tid < 96) {
            const float4 v = __ldg(reinterpret_cast<const float4*>(
                                       xs + (size_t)p0 * 3) + tid);
            reinterpret_cast<float4*>(sbuf)[tid] = v;
        }
        __syncthreads();
        px = sbuf[tid * 3 + 0];
        py = sbuf[tid * 3 + 1];
        pz = sbuf[tid * 3 + 2];
        __syncthreads();
    } else {
        const int ptc = (pt < n) ? pt : (n - 1);
        px = xs[(size_t)ptc * 3 + 0];
        py = xs[(size_t)ptc * 3 + 1];
        pz = xs[(size_t)ptc * 3 + 2];
    }

    // ---- Dense levels 0..4 via 2x2 patch table: 2 x LDG.128 each ----
    #pragma unroll 1
    for (int l = 0; l < NUM_DENSE; ++l) {
        const uint4* __restrict__ dtab = g_dpatch + lp.doff[l];
        const float scale = lp.scale[l];
        const int   res   = lp.res[l];

        // Unfused mul+add to match reference elementwise x*scale + 0.5.
        const float posx = __fadd_rn(__fmul_rn(px, scale), 0.5f);
        const float posy = __fadd_rn(__fmul_rn(py, scale), 0.5f);
        const float posz = __fadd_rn(__fmul_rn(pz, scale), 0.5f);
        const float pfx = floorf(posx), pfy = floorf(posy), pfz = floorf(posz);
        const float fx = posx - pfx, fy = posy - pfy, fz = posz - pfz;
        const int gx = (int)pfx, gy = (int)pfy, gz = (int)pfz;
        // Base coords are always in [0, res-1]; +1 clamps baked into table.
        const int r2   = res * res;
        const int base = gx + gy * res + gz * r2;
        const int z1   = min(gz + 1, res - 1) * r2 + gx + gy * res;

        const uint4 q0 = __ldg(dtab + base);   // z0 plane: 4 xy-corners
        const uint4 q1 = __ldg(dtab + z1);     // z1 plane

        float2 f[8];
        f[0] = h2f(q0.x); f[1] = h2f(q1.x);    // x0y0 z0/z1
        f[2] = h2f(q0.z); f[3] = h2f(q1.z);    // x0y1
        f[4] = h2f(q0.y); f[5] = h2f(q1.y);    // x1y0
        f[6] = h2f(q0.w); f[7] = h2f(q1.w);    // x1y1

        float2 r = blend8v(f, fx, fy, fz);
        sbuf[tid * 33 + 2 * l + 0] = r.x;
        sbuf[tid * 33 + 2 * l + 1] = r.y;
    }

    // ---- Hash levels 5..15: idx = (x ^ y*P1 ^ z*P2) & mask, fp16 table ----
    // Partner (x+1) index = a ^ m, m = hx ^ (hx+1). When m<=3 (prob 3/4) the
    // partner is in the same aligned 4-entry (16B) group -> one LDG.128.
    #pragma unroll 2
    for (int l = NUM_DENSE; l < L_LEVELS; ++l) {
        const unsigned* __restrict__ tbl =
            g_hash + (size_t)(l - NUM_DENSE) * HASHMAP_SZ;
        const float scale = lp.scale[l];

        const float posx = __fadd_rn(__fmul_rn(px, scale), 0.5f);
        const float posy = __fadd_rn(__fmul_rn(py, scale), 0.5f);
        const float posz = __fadd_rn(__fmul_rn(pz, scale), 0.5f);
        const float pfx = floorf(posx), pfy = floorf(posy), pfz = floorf(posz);
        const float fx = posx - pfx, fy = posy - pfy, fz = posz - pfz;

        const unsigned hx0 = (unsigned)(int)pfx;
        const unsigned hx1 = hx0 + 1u;
        const unsigned hy0 = (unsigned)(int)pfy * PRIME_Y;
        const unsigned hy1 = hy0 + PRIME_Y;
        const unsigned hz0 = (unsigned)(int)pfz * PRIME_Z;
        const unsigned hz1 = hz0 + PRIME_Z;

        const unsigned hyz0 = hy0 ^ hz0;
        const unsigned hyz1 = hy0 ^ hz1;
        const unsigned hyz2 = hy1 ^ hz0;
        const unsigned hyz3 = hy1 ^ hz1;

        const unsigned m = hx0 ^ hx1;          // 1,3,7,15,... (low ones-run)

        float2 f[8];
        if (m <= 3u) {
            // Both x-corners per (y,z) in one aligned 16B group.
            const uint4* __restrict__ t4 =
                reinterpret_cast<const uint4*>(tbl);
            const unsigned a0 = (hx0 ^ hyz0) & HASH_MASK;
            const unsigned a1 = (hx0 ^ hyz1) & HASH_MASK;
            const unsigned a2 = (hx0 ^ hyz2) & HASH_MASK;
            const unsigned a3 = (hx0 ^ hyz3) & HASH_MASK;
            const uint4 q0 = __ldg(t4 + (a0 >> 2));
            const uint4 q1 = __ldg(t4 + (a1 >> 2));
            const uint4 q2 = __ldg(t4 + (a2 >> 2));
            const uint4 q3 = __ldg(t4 + (a3 >> 2));
            const unsigned j0 = a0 & 3u, j1 = a1 & 3u;
            const unsigned j2 = a2 & 3u, j3 = a3 & 3u;
            f[0] = h2f(comp4(q0, j0)); f[4] = h2f(comp4(q0, j0 ^ m));
            f[1] = h2f(comp4(q1, j1)); f[5] = h2f(comp4(q1, j1 ^ m));
            f[2] = h2f(comp4(q2, j2)); f[6] = h2f(comp4(q2, j2 ^ m));
            f[3] = h2f(comp4(q3, j3)); f[7] = h2f(comp4(q3, j3 ^ m));
        } else {
            f[0] = h2f(__ldg(tbl + ((hx0 ^ hyz0) & HASH_MASK)));
            f[1] = h2f(__ldg(tbl + ((hx0 ^ hyz1) & HASH_MASK)));
            f[2] = h2f(__ldg(tbl + ((hx0 ^ hyz2) & HASH_MASK)));
            f[3] = h2f(__ldg(tbl + ((hx0 ^ hyz3) & HASH_MASK)));
            f[4] = h2f(__ldg(tbl + ((hx1 ^ hyz0) & HASH_MASK)));
            f[5] = h2f(__ldg(tbl + ((hx1 ^ hyz1) & HASH_MASK)));
            f[6] = h2f(__ldg(tbl + ((hx1 ^ hyz2) & HASH_MASK)));
            f[7] = h2f(__ldg(tbl + ((hx1 ^ hyz3) & HASH_MASK)));
        }

        float2 r = blend8v(f, fx, fy, fz);
        sbuf[tid * 33 + 2 * l + 0] = r.x;
        sbuf[tid * 33 + 2 * l + 1] = r.y;
    }

    __syncthreads();

    // Coalesced copy-out; streaming stores keep tables resident in L2.
    const int nvalid = min(BLOCK_T, n - p0);
    float* __restrict__ ob = out + (size_t)p0 * 32;
    const int total = nvalid * 32;
    #pragma unroll 4
    for (int k = tid; k < total; k += BLOCK_T) {
        __stcs(ob + k, sbuf[(k >> 5) * 33 + (k & 31)]);
    }
}

extern "C" void kernel_launch(void* const* d_in, const int* in_sizes, int n_in,
                              void* d_out, int out_size)
{
    const int n = out_size / (L_LEVELS * 2);   // out is [N, 32] float32

    const float* x   = (const float*)d_in[0];
    const float* tbl = (const float*)d_in[1];
    if (n_in >= 2 && in_sizes[0] != n * 3) {
        x   = (const float*)d_in[1];
        tbl = (const float*)d_in[0];
    }

    LevelParams lp;
    const double B = pow(2.0, 7.0 / 15.0);     // log2(2048/16)/15
    int off = 0;
    for (int l = 0; l < L_LEVELS; ++l) {
        const double s = 16.0 * pow(B, (double)l) - 1.0;
        lp.scale[l] = (float)s;
        lp.res[l]   = (int)ceil(s) + 1;
        if (l < NUM_DENSE) {
            lp.doff[l] = off;
            off += lp.res[l] * lp.res[l] * lp.res[l];
        }
    }
    const int dense_total = off;               // 330,940

    // Prologues (same graph, deterministic pure functions of inputs).
    const int htot = NUM_HASH * (int)HASHMAP_SZ;
    build_hash_kernel<<<(htot + 255) / 256, 256>>>(tbl);
    build_dense_kernel<<<(dense_total + 255) / 256, 256>>>(tbl, lp, dense_total);

    const int grid = (n + BLOCK_T - 1) / BLOCK_T;
    hashgrid_kernel<<<grid, BLOCK_T>>>(x, (float*)d_out, n, lp);
}

// round 8
// speedup vs baseline: 3.7829x; 1.8691x over previous
#include <cuda_runtime.h>
#include <cuda_fp16.h>
#include <math.h>

// TropicalHashGrid: 16-level hash-grid encoding, N=2^21 points, F=2 feats/level.
// Levels 0-4 dense, levels 5-15 spatially hashed. fp16 tables (tcnn-style).
//
// R8 changes vs R7 (879us, rel_err 2.3e-4; ~70 scattered wavefronts/point):
//  - dense: 32B cube entries (all 8 clamped corners); lane pairs load the two
//    16B halves of one entry in one LDG.128 -> same 128B line -> 1 wf/pt/level
//    (was 2). Partial blends combined via shfl_xor(1).
//  - hash: second table copy shifted by 2 entries; pairs that straddle an
//    aligned-4 boundary but fit a 2-mod-4 window load from copy B.
//    E[wf]/level 5 -> ~4.69.

#define L_LEVELS   16
#define HASHMAP_SZ (1u << 19)
#define HASH_MASK  (HASHMAP_SZ - 1u)
#define GROUPS_PER (HASHMAP_SZ / 4)
#define PRIME_Y    2654435761u
#define PRIME_Z    805459861u
#define NUM_DENSE  5
#define NUM_HASH   (L_LEVELS - NUM_DENSE)
#define BLOCK_T    128

// Scratch (static __device__: allocation-free).
// Dense cube table: 330,940 entries * 32B = 10.6MB
#define DENSE_TOTAL_MAX 340000
__device__ __align__(128) uint4 g_dcube[2 * DENSE_TOTAL_MAX];
// fp16 hash tables: copy A (natural) + copy B (shifted by 2 entries), 23MB each
__device__ __align__(16) unsigned g_hash [NUM_HASH * HASHMAP_SZ];
__device__ __align__(16) uint4    g_hashB[NUM_HASH * GROUPS_PER];

struct LevelParams {
    float scale[L_LEVELS];
    int   res[L_LEVELS];
    int   doff[NUM_DENSE];
};

// ------------- bit-cast helpers -------------
__device__ __forceinline__ unsigned h2_to_u(__half2 h) {
    return *reinterpret_cast<unsigned*>(&h);
}
__device__ __forceinline__ float2 h2f(unsigned u) {
    return __half22float2(*reinterpret_cast<__half2*>(&u));
}
// Select component j (0..3) of a uint4.
__device__ __forceinline__ unsigned comp4(const uint4 q, unsigned j) {
    const unsigned lo = (j & 1u) ? q.y : q.x;
    const unsigned hi = (j & 1u) ? q.w : q.z;
    return (j & 2u) ? hi : lo;
}

// ------------- prologue 1: fp16 hash tables (copy A) -------------
__global__ void build_hash_kernel(const float* __restrict__ table)
{
    const int i = blockIdx.x * blockDim.x + threadIdx.x;
    if (i >= NUM_HASH * (int)HASHMAP_SZ) return;
    const int lvl = i >> 19;
    const int idx = i & (int)HASH_MASK;
    const float2 v = reinterpret_cast<const float2*>(table)
                         [(size_t)(lvl + NUM_DENSE) * HASHMAP_SZ + idx];
    g_hash[i] = h2_to_u(__floats2half2_rn(v.x, v.y));
}

// ------------- prologue 2: shifted copy B from copy A -------------
// B[lvl][j] packs entries (4j+2 .. 4j+5) & mask of level lvl.
__global__ void build_hashB_kernel()
{
    const int i = blockIdx.x * blockDim.x + threadIdx.x;
    if (i >= NUM_HASH * GROUPS_PER) return;
    const int lvl = i / GROUPS_PER;
    const int j   = i - lvl * GROUPS_PER;
    const unsigned* src = g_hash + (size_t)lvl * HASHMAP_SZ;
    uint4 q;
    q.x = src[(4u * j + 2u) & HASH_MASK];
    q.y = src[(4u * j + 3u) & HASH_MASK];
    q.z = src[(4u * j + 4u) & HASH_MASK];
    q.w = src[(4u * j + 5u) & HASH_MASK];
    g_hashB[i] = q;
}

// ------------- prologue 3: dense cube table -------------
// entry(x,y,z), half h: 4 half2 corners {(x,y),(x1,y),(x,y1),(x1,y1)} at
// z-plane (h ? z1 : z), with all +1 clamps to res-1 baked in.
__global__ void build_dense_kernel(const float* __restrict__ table,
                                   LevelParams lp, int total)
{
    const int i = blockIdx.x * blockDim.x + threadIdx.x;
    if (i >= total) return;
    int l = 0;
    #pragma unroll
    for (int k = 1; k < NUM_DENSE; ++k) if (i >= lp.doff[k]) l = k;
    const int flat = i - lp.doff[l];
    const int res  = lp.res[l];
    const int r2   = res * res;
    const int z    = flat / r2;
    const int rem  = flat - z * r2;
    const int y    = rem / res;
    const int x    = rem - y * res;
    const int x1   = min(x + 1, res - 1);
    const int y1   = min(y + 1, res - 1);
    const int z1   = min(z + 1, res - 1);
    const float2* __restrict__ tbl =
        reinterpret_cast<const float2*>(table) + (size_t)l * HASHMAP_SZ;
    #pragma unroll
    for (int h = 0; h < 2; ++h) {
        const int zz = (h ? z1 : z) * r2;
        const float2 c00 = tbl[x  + y  * res + zz];
        const float2 c10 = tbl[x1 + y  * res + zz];
        const float2 c01 = tbl[x  + y1 * res + zz];
        const float2 c11 = tbl[x1 + y1 * res + zz];
        uint4 q;
        q.x = h2_to_u(__floats2half2_rn(c00.x, c00.y));
        q.y = h2_to_u(__floats2half2_rn(c10.x, c10.y));
        q.z = h2_to_u(__floats2half2_rn(c01.x, c01.y));
        q.w = h2_to_u(__floats2half2_rn(c11.x, c11.y));
        g_dcube[2 * i + h] = q;
    }
}

// ------------- main kernel -------------
__global__ void __launch_bounds__(BLOCK_T, 8)
hashgrid_kernel(const float* __restrict__ xs,
                float* __restrict__ out,
                int n, LevelParams lp)
{
    __shared__ float sbuf[BLOCK_T * 33];   // coords, then results (stride 33)

    const int tid  = threadIdx.x;
    const int lane = tid & 31;
    const int wrow = (tid >> 5) * 32;      // warp's first row within block
    const int p0   = blockIdx.x * BLOCK_T;
    const int pt   = p0 + tid;

    float px, py, pz;
    if (p0 + BLOCK_T <= n) {
        if (tid < 96) {
            const float4 v = __ldg(reinterpret_cast<const float4*>(
                                       xs + (size_t)p0 * 3) + tid);
            reinterpret_cast<float4*>(sbuf)[tid] = v;
        }
        __syncthreads();
        px = sbuf[tid * 3 + 0];
        py = sbuf[tid * 3 + 1];
        pz = sbuf[tid * 3 + 2];
        __syncthreads();
    } else {
        const int ptc = (pt < n) ? pt : (n - 1);
        px = xs[(size_t)ptc * 3 + 0];
        py = xs[(size_t)ptc * 3 + 1];
        pz = xs[(size_t)ptc * 3 + 2];
    }

    // ---- Dense levels 0..4: 32B cube entry, lane-pair cooperative load ----
    #pragma unroll 1
    for (int l = 0; l < NUM_DENSE; ++l) {
        const float scale = lp.scale[l];
        const int   res   = lp.res[l];

        // Unfused mul+add to match reference elementwise x*scale + 0.5.
        const float posx = __fadd_rn(__fmul_rn(px, scale), 0.5f);
        const float posy = __fadd_rn(__fmul_rn(py, scale), 0.5f);
        const float posz = __fadd_rn(__fmul_rn(pz, scale), 0.5f);
        const float pfx = floorf(posx), pfy = floorf(posy), pfz = floorf(posz);
        const float fx = posx - pfx, fy = posy - pfy, fz = posz - pfz;
        const int gx = (int)pfx, gy = (int)pfy, gz = (int)pfz;
        const int base = lp.doff[l] + gx + (gy + gz * res) * res;

        // Two passes; pass p covers warp points q = 16p .. 16p+15.
        // Lanes (2k, 2k+1) load the two 16B halves of point q's cube entry
        // (same 128B line -> one wavefront per pair).
        #pragma unroll
        for (int p = 0; p < 2; ++p) {
            const int   q   = 16 * p + (lane >> 1);
            const int   bq  = __shfl_sync(0xffffffffu, base, q);
            const float qfx = __shfl_sync(0xffffffffu, fx, q);
            const float qfy = __shfl_sync(0xffffffffu, fy, q);
            const float qfz = __shfl_sync(0xffffffffu, fz, q);

            const uint4 h = __ldg(g_dcube + 2 * bq + (lane & 1));

            const float wz  = (lane & 1) ? qfz : (1.0f - qfz);
            const float wx1 = qfx, wx0 = 1.0f - qfx;
            const float wy1 = qfy, wy0 = 1.0f - qfy;
            const float w00 = wx0 * wy0 * wz, w10 = wx1 * wy0 * wz;
            const float w01 = wx0 * wy1 * wz, w11 = wx1 * wy1 * wz;
            const float2 c00 = h2f(h.x), c10 = h2f(h.y);
            const float2 c01 = h2f(h.z), c11 = h2f(h.w);

            float rx = w00 * c00.x;
            float ry = w00 * c00.y;
            rx = fmaf(w10, c10.x, rx); ry = fmaf(w10, c10.y, ry);
            rx = fmaf(w01, c01.x, rx); ry = fmaf(w01, c01.y, ry);
            rx = fmaf(w11, c11.x, rx); ry = fmaf(w11, c11.y, ry);

            rx += __shfl_xor_sync(0xffffffffu, rx, 1);
            ry += __shfl_xor_sync(0xffffffffu, ry, 1);

            if ((lane & 1) == 0) {
                const int row = wrow + q;
                sbuf[row * 33 + 2 * l + 0] = rx;
                sbuf[row * 33 + 2 * l + 1] = ry;
            }
        }
    }

    // ---- Hash levels 5..15: idx = (x ^ y*P1 ^ z*P2) & mask ----
    // Per (y,z) combo the two x-corners a, b=a^m: load one 16B group from
    // copy A if same aligned-4 group, copy B (shifted by 2) if same 2-mod-4
    // window, else 2 scalar loads.
    #pragma unroll 1
    for (int l = NUM_DENSE; l < L_LEVELS; ++l) {
        const unsigned* __restrict__ tbl =
            g_hash + (size_t)(l - NUM_DENSE) * HASHMAP_SZ;
        const uint4* __restrict__ tA = reinterpret_cast<const uint4*>(tbl);
        const uint4* __restrict__ tB =
            g_hashB + (size_t)(l - NUM_DENSE) * GROUPS_PER;
        const float scale = lp.scale[l];

        const float posx = __fadd_rn(__fmul_rn(px, scale), 0.5f);
        const float posy = __fadd_rn(__fmul_rn(py, scale), 0.5f);
        const float posz = __fadd_rn(__fmul_rn(pz, scale), 0.5f);
        const float pfx = floorf(posx), pfy = floorf(posy), pfz = floorf(posz);
        const float fx = posx - pfx, fy = posy - pfy, fz = posz - pfz;

        const unsigned hx0 = (unsigned)(int)pfx;
        const unsigned hx1 = hx0 + 1u;
        const unsigned hy0 = (unsigned)(int)pfy * PRIME_Y;
        const unsigned hy1 = hy0 + PRIME_Y;
        const unsigned hz0 = (unsigned)(int)pfz * PRIME_Z;
        const unsigned hz1 = hz0 + PRIME_Z;

        unsigned av[4], bv[4], s0[4], s1[4];
        const uint4* gp[4];
        bool pr[4];
        {
            const unsigned hyz[4] = { hy0 ^ hz0, hy0 ^ hz1,
                                      hy1 ^ hz0, hy1 ^ hz1 };
            #pragma unroll
            for (int c = 0; c < 4; ++c) {
                const unsigned a = (hx0 ^ hyz[c]) & HASH_MASK;
                const unsigned b = (hx1 ^ hyz[c]) & HASH_MASK;
                av[c] = a; bv[c] = b;
                const unsigned am2 = a - 2u, bm2 = b - 2u;
                const bool pA = (a >> 2) == (b >> 2);
                const bool pB = (am2 >> 2) == (bm2 >> 2);
                pr[c] = pA || pB;
                gp[c] = pA ? (tA + (a >> 2)) : (tB + (am2 >> 2));
                s0[c] = pA ? (a & 3u) : (am2 & 3u);
                s1[c] = pA ? (b & 3u) : (bm2 & 3u);
            }
        }

        // Issue all loads back-to-back (predicated) to keep MLP high.
        uint4 qv[4];
        #pragma unroll
        for (int c = 0; c < 4; ++c) if (pr[c]) qv[c] = __ldg(gp[c]);
        unsigned u0[4], u1[4];
        #pragma unroll
        for (int c = 0; c < 4; ++c) {
            if (!pr[c]) {
                u0[c] = __ldg(tbl + av[c]);
                u1[c] = __ldg(tbl + bv[c]);
            }
        }

        float2 f[8];
        #pragma unroll
        for (int c = 0; c < 4; ++c) {
            if (pr[c]) {
                f[c]     = h2f(comp4(qv[c], s0[c]));
                f[4 + c] = h2f(comp4(qv[c], s1[c]));
            } else {
                f[c]     = h2f(u0[c]);
                f[4 + c] = h2f(u1[c]);
            }
        }

        // Trilinear blend (z fastest among the 4 combos, x split at f[4..7]).
        const float wx1 = fx, wx0 = 1.0f - fx;
        const float wy1 = fy, wy0 = 1.0f - fy;
        const float wz1 = fz, wz0 = 1.0f - fz;
        const float wxy00 = wx0 * wy0, wxy01 = wx0 * wy1;
        const float wxy10 = wx1 * wy0, wxy11 = wx1 * wy1;
        float w[8];
        w[0] = wxy00 * wz0; w[1] = wxy00 * wz1;
        w[2] = wxy01 * wz0; w[3] = wxy01 * wz1;
        w[4] = wxy10 * wz0; w[5] = wxy10 * wz1;
        w[6] = wxy11 * wz0; w[7] = wxy11 * wz1;

        float r0 = w[0] * f[0].x;
        float r1 = w[0] * f[0].y;
        #pragma unroll
        for (int j = 1; j < 8; ++j) {
            r0 = fmaf(w[j], f[j].x, r0);
            r1 = fmaf(w[j], f[j].y, r1);
        }

        sbuf[tid * 33 + 2 * l + 0] = r0;
        sbuf[tid * 33 + 2 * l + 1] = r1;
    }

    __syncthreads();

    // Coalesced copy-out; streaming stores keep tables resident in L2.
    const int nvalid = min(BLOCK_T, n - p0);
    float* __restrict__ ob = out + (size_t)p0 * 32;
    const int total = nvalid * 32;
    #pragma unroll 4
    for (int k = tid; k < total; k += BLOCK_T) {
        __stcs(ob + k, sbuf[(k >> 5) * 33 + (k & 31)]);
    }
}

extern "C" void kernel_launch(void* const* d_in, const int* in_sizes, int n_in,
                              void* d_out, int out_size)
{
    const int n = out_size / (L_LEVELS * 2);   // out is [N, 32] float32

    const float* x   = (const float*)d_in[0];
    const float* tbl = (const float*)d_in[1];
    if (n_in >= 2 && in_sizes[0] != n * 3) {
        x   = (const float*)d_in[1];
        tbl = (const float*)d_in[0];
    }

    LevelParams lp;
    const double B = pow(2.0, 7.0 / 15.0);     // log2(2048/16)/15
    int off = 0;
    for (int l = 0; l < L_LEVELS; ++l) {
        const double s = 16.0 * pow(B, (double)l) - 1.0;
        lp.scale[l] = (float)s;
        lp.res[l]   = (int)ceil(s) + 1;
        if (l < NUM_DENSE) {
            lp.doff[l] = off;
            off += lp.res[l] * lp.res[l] * lp.res[l];
        }
    }
    const int dense_total = off;               // 330,940

    // Prologues (ordered on one stream; deterministic functions of inputs).
    const int htot = NUM_HASH * (int)HASHMAP_SZ;
    build_hash_kernel<<<(htot + 255) / 256, 256>>>(tbl);
    const int btot = NUM_HASH * GROUPS_PER;
    build_hashB_kernel<<<(btot + 255) / 256, 256>>>();
    build_dense_kernel<<<(dense_total + 255) / 256, 256>>>(tbl, lp, dense_total);

    const int grid = (n + BLOCK_T - 1) / BLOCK_T;
    hashgrid_kernel<<<grid, BLOCK_T>>>(x, (float*)d_out, n, lp);
}

// round 9
// speedup vs baseline: 3.7929x; 1.0027x over previous
#include <cuda_runtime.h>
#include <cuda_fp16.h>
#include <math.h>

// TropicalHashGrid: 16-level hash-grid encoding, N=2^21 points, F=2 feats/level.
// Levels 0-5 handled via dense cube tables (level 5 baked from its hash),
// levels 6-15 spatially hashed. fp16 tables (tcnn-style).
//
// R9 changes vs R8 (470us, L1=85.3%, occ=48.9%, regs=63):
//  - level 5 (res=81, 531K cells) densified: prologue bakes its 8 hash-gathered
//    corners per cell into the 32B cube format -> 1 wf/pt (was ~4.5)
//  - copy-B built inside build_hash (B[w] = A[(w+2)&MASK]); arrays 10 levels
//  - __launch_bounds__(128, 9): 56-reg cap -> 9 CTAs/SM

#define L_LEVELS   16
#define HASHMAP_SZ (1u << 19)
#define HASH_MASK  (HASHMAP_SZ - 1u)
#define PRIME_Y    2654435761u
#define PRIME_Z    805459861u
#define NUM_DENSE  6                        // levels 0..5 via cube tables
#define NUM_HASH   (L_LEVELS - NUM_DENSE)   // 10
#define BLOCK_T    128

// Scratch (static __device__: allocation-free).
// Cube tables: levels 0-4 = 330,940 cells + level 5 = 531,441 -> 862,381 * 32B = 27.6MB
#define DENSE_TOTAL_MAX 871000
__device__ __align__(128) uint4 g_dcube[2 * DENSE_TOTAL_MAX];
// fp16 hash tables, copy A (natural) and copy B (shifted by 2 words): 20MB each
__device__ __align__(16) unsigned g_hash [NUM_HASH * HASHMAP_SZ];
__device__ __align__(16) unsigned g_hashB[NUM_HASH * HASHMAP_SZ];

struct LevelParams {
    float scale[L_LEVELS];
    int   res[L_LEVELS];
    int   doff[NUM_DENSE];
};

// ------------- bit-cast helpers -------------
__device__ __forceinline__ unsigned h2_to_u(__half2 h) {
    return *reinterpret_cast<unsigned*>(&h);
}
__device__ __forceinline__ float2 h2f(unsigned u) {
    return __half22float2(*reinterpret_cast<__half2*>(&u));
}
// Select component j (0..3) of a uint4.
__device__ __forceinline__ unsigned comp4(const uint4 q, unsigned j) {
    const unsigned lo = (j & 1u) ? q.y : q.x;
    const unsigned hi = (j & 1u) ? q.w : q.z;
    return (j & 2u) ? hi : lo;
}

// ------------- prologue 1: fp16 hash tables, copies A and B -------------
// B is A shifted by 2 words: B[w] = A[(w+2) & MASK].
__global__ void build_hash_kernel(const float* __restrict__ table)
{
    const int i = blockIdx.x * blockDim.x + threadIdx.x;
    if (i >= NUM_HASH * (int)HASHMAP_SZ) return;
    const int lvl = i >> 19;                 // 0..9 -> level 6..15
    const unsigned idx = (unsigned)i & HASH_MASK;
    const float2 v = reinterpret_cast<const float2*>(table)
                         [(size_t)(lvl + NUM_DENSE) * HASHMAP_SZ + idx];
    const unsigned u = h2_to_u(__floats2half2_rn(v.x, v.y));
    g_hash [(size_t)lvl * HASHMAP_SZ + idx] = u;
    g_hashB[(size_t)lvl * HASHMAP_SZ + ((idx - 2u) & HASH_MASK)] = u;
}

// ------------- prologue 2: cube tables for clamped dense levels 0-4 -------------
// entry(x,y,z), half h: 4 half2 corners {(x,y),(x1,y),(x,y1),(x1,y1)} at
// z-plane (h ? z1 : z), with all +1 clamps to res-1 baked in.
__global__ void build_dense_kernel(const float* __restrict__ table,
                                   LevelParams lp, int total)
{
    const int i = blockIdx.x * blockDim.x + threadIdx.x;
    if (i >= total) return;
    int l = 0;
    #pragma unroll
    for (int k = 1; k < 5; ++k) if (i >= lp.doff[k]) l = k;
    const int flat = i - lp.doff[l];
    const int res  = lp.res[l];
    const int r2   = res * res;
    const int z    = flat / r2;
    const int rem  = flat - z * r2;
    const int y    = rem / res;
    const int x    = rem - y * res;
    const int x1   = min(x + 1, res - 1);
    const int y1   = min(y + 1, res - 1);
    const int z1   = min(z + 1, res - 1);
    const float2* __restrict__ tbl =
        reinterpret_cast<const float2*>(table) + (size_t)l * HASHMAP_SZ;
    #pragma unroll
    for (int h = 0; h < 2; ++h) {
        const int zz = (h ? z1 : z) * r2;
        const float2 c00 = tbl[x  + y  * res + zz];
        const float2 c10 = tbl[x1 + y  * res + zz];
        const float2 c01 = tbl[x  + y1 * res + zz];
        const float2 c11 = tbl[x1 + y1 * res + zz];
        uint4 q;
        q.x = h2_to_u(__floats2half2_rn(c00.x, c00.y));
        q.y = h2_to_u(__floats2half2_rn(c10.x, c10.y));
        q.z = h2_to_u(__floats2half2_rn(c01.x, c01.y));
        q.w = h2_to_u(__floats2half2_rn(c11.x, c11.y));
        g_dcube[2 * i + h] = q;
    }
}

// ------------- prologue 3: cube table for level 5 (hashed corners) -------------
// Level 5 is semantically hashed (81^3 > 2^19): bake tbl[hash(corner)] per cell.
// No clamping; corner coords go straight through the spatial hash.
__global__ void build_dense5_kernel(const float* __restrict__ table,
                                    int res, int doff5, int total)
{
    const int i = blockIdx.x * blockDim.x + threadIdx.x;
    if (i >= total) return;
    const int r2  = res * res;
    const int z   = i / r2;
    const int rem = i - z * r2;
    const int y   = rem / res;
    const int x   = rem - y * res;
    const float2* __restrict__ tbl =
        reinterpret_cast<const float2*>(table) + (size_t)5 * HASHMAP_SZ;
    const unsigned hx0 = (unsigned)x,            hx1 = hx0 + 1u;
    const unsigned hy0 = (unsigned)y * PRIME_Y,  hy1 = hy0 + PRIME_Y;
    #pragma unroll
    for (int h = 0; h < 2; ++h) {
        const unsigned hz = ((unsigned)z + (unsigned)h) * PRIME_Z;
        const float2 c00 = tbl[(hx0 ^ hy0 ^ hz) & HASH_MASK];
        const float2 c10 = tbl[(hx1 ^ hy0 ^ hz) & HASH_MASK];
        const float2 c01 = tbl[(hx0 ^ hy1 ^ hz) & HASH_MASK];
        const float2 c11 = tbl[(hx1 ^ hy1 ^ hz) & HASH_MASK];
        uint4 q;
        q.x = h2_to_u(__floats2half2_rn(c00.x, c00.y));
        q.y = h2_to_u(__floats2half2_rn(c10.x, c10.y));
        q.z = h2_to_u(__floats2half2_rn(c01.x, c01.y));
        q.w = h2_to_u(__floats2half2_rn(c11.x, c11.y));
        g_dcube[2 * (doff5 + i) + h] = q;
    }
}

// ------------- main kernel -------------
__global__ void __launch_bounds__(BLOCK_T, 9)
hashgrid_kernel(const float* __restrict__ xs,
                float* __restrict__ out,
                int n, LevelParams lp)
{
    __shared__ float sbuf[BLOCK_T * 33];   // coords, then results (stride 33)

    const int tid  = threadIdx.x;
    const int lane = tid & 31;
    const int wrow = (tid >> 5) * 32;      // warp's first row within block
    const int p0   = blockIdx.x * BLOCK_T;
    const int pt   = p0 + tid;

    float px, py, pz;
    if (p0 + BLOCK_T <= n) {
        if (tid < 96) {
            const float4 v = __ldg(reinterpret_cast<const float4*>(
                                       xs + (size_t)p0 * 3) + tid);
            reinterpret_cast<float4*>(sbuf)[tid] = v;
        }
        __syncthreads();
        px = sbuf[tid * 3 + 0];
        py = sbuf[tid * 3 + 1];
        pz = sbuf[tid * 3 + 2];
        __syncthreads();
    } else {
        const int ptc = (pt < n) ? pt : (n - 1);
        px = xs[(size_t)ptc * 3 + 0];
        py = xs[(size_t)ptc * 3 + 1];
        pz = xs[(size_t)ptc * 3 + 2];
    }

    // ---- Dense-treated levels 0..5: 32B cube entry, lane-pair loads ----
    #pragma unroll 1
    for (int l = 0; l < NUM_DENSE; ++l) {
        const float scale = lp.scale[l];
        const int   res   = lp.res[l];

        // Unfused mul+add to match reference elementwise x*scale + 0.5.
        const float posx = __fadd_rn(__fmul_rn(px, scale), 0.5f);
        const float posy = __fadd_rn(__fmul_rn(py, scale), 0.5f);
        const float posz = __fadd_rn(__fmul_rn(pz, scale), 0.5f);
        const float pfx = floorf(posx), pfy = floorf(posy), pfz = floorf(posz);
        const float fx = posx - pfx, fy = posy - pfy, fz = posz - pfz;
        const int gx = (int)pfx, gy = (int)pfy, gz = (int)pfz;
        // Base coords always in [0, res-1]; neighbor handling baked in table.
        const int base = lp.doff[l] + gx + (gy + gz * res) * res;

        // Two passes; pass p covers warp points q = 16p .. 16p+15.
        // Lanes (2k, 2k+1) load the two 16B halves of point q's cube entry
        // (same 128B line -> one wavefront per pair).
        #pragma unroll
        for (int p = 0; p < 2; ++p) {
            const int   q   = 16 * p + (lane >> 1);
            const int   bq  = __shfl_sync(0xffffffffu, base, q);
            const float qfx = __shfl_sync(0xffffffffu, fx, q);
            const float qfy = __shfl_sync(0xffffffffu, fy, q);
            const float qfz = __shfl_sync(0xffffffffu, fz, q);

            const uint4 h = __ldg(g_dcube + 2 * bq + (lane & 1));

            const float wz  = (lane & 1) ? qfz : (1.0f - qfz);
            const float wx1 = qfx, wx0 = 1.0f - qfx;
            const float wy1 = qfy, wy0 = 1.0f - qfy;
            const float w00 = wx0 * wy0 * wz, w10 = wx1 * wy0 * wz;
            const float w01 = wx0 * wy1 * wz, w11 = wx1 * wy1 * wz;
            const float2 c00 = h2f(h.x), c10 = h2f(h.y);
            const float2 c01 = h2f(h.z), c11 = h2f(h.w);

            float rx = w00 * c00.x;
            float ry = w00 * c00.y;
            rx = fmaf(w10, c10.x, rx); ry = fmaf(w10, c10.y, ry);
            rx = fmaf(w01, c01.x, rx); ry = fmaf(w01, c01.y, ry);
            rx = fmaf(w11, c11.x, rx); ry = fmaf(w11, c11.y, ry);

            rx += __shfl_xor_sync(0xffffffffu, rx, 1);
            ry += __shfl_xor_sync(0xffffffffu, ry, 1);

            if ((lane & 1) == 0) {
                const int row = wrow + q;
                sbuf[row * 33 + 2 * l + 0] = rx;
                sbuf[row * 33 + 2 * l + 1] = ry;
            }
        }
    }

    // ---- Hash levels 6..15: idx = (x ^ y*P1 ^ z*P2) & mask ----
    // Per (y,z) combo the two x-corners a, b=a^m: one 16B group load from
    // copy A if same aligned-4 group, copy B (shifted by 2) if same 2-mod-4
    // window, else 2 scalar loads. All loads predicated (no divergence).
    #pragma unroll 1
    for (int l = NUM_DENSE; l < L_LEVELS; ++l) {
        const unsigned* __restrict__ tbl =
            g_hash + (size_t)(l - NUM_DENSE) * HASHMAP_SZ;
        const uint4* __restrict__ tA = reinterpret_cast<const uint4*>(tbl);
        const uint4* __restrict__ tB = reinterpret_cast<const uint4*>(
            g_hashB + (size_t)(l - NUM_DENSE) * HASHMAP_SZ);
        const float scale = lp.scale[l];

        const float posx = __fadd_rn(__fmul_rn(px, scale), 0.5f);
        const float posy = __fadd_rn(__fmul_rn(py, scale), 0.5f);
        const float posz = __fadd_rn(__fmul_rn(pz, scale), 0.5f);
        const float pfx = floorf(posx), pfy = floorf(posy), pfz = floorf(posz);
        const float fx = posx - pfx, fy = posy - pfy, fz = posz - pfz;

        const unsigned hx0 = (unsigned)(int)pfx;
        const unsigned hx1 = hx0 + 1u;
        const unsigned hy0 = (unsigned)(int)pfy * PRIME_Y;
        const unsigned hy1 = hy0 + PRIME_Y;
        const unsigned hz0 = (unsigned)(int)pfz * PRIME_Z;
        const unsigned hz1 = hz0 + PRIME_Z;

        unsigned av[4], bv[4], s0[4], s1[4];
        const uint4* gp[4];
        bool pr[4];
        {
            const unsigned hyz[4] = { hy0 ^ hz0, hy0 ^ hz1,
                                      hy1 ^ hz0, hy1 ^ hz1 };
            #pragma unroll
            for (int c = 0; c < 4; ++c) {
                const unsigned a = (hx0 ^ hyz[c]) & HASH_MASK;
                const unsigned b = (hx1 ^ hyz[c]) & HASH_MASK;
                av[c] = a; bv[c] = b;
                const unsigned am2 = a - 2u, bm2 = b - 2u;
                const bool pA = (a >> 2) == (b >> 2);
                const bool pB = (am2 >> 2) == (bm2 >> 2);
                pr[c] = pA || pB;
                gp[c] = pA ? (tA + (a >> 2)) : (tB + ((am2 & HASH_MASK) >> 2));
                s0[c] = pA ? (a & 3u) : (am2 & 3u);
                s1[c] = pA ? (b & 3u) : (bm2 & 3u);
            }
        }

        // Issue all loads back-to-back (predicated) to keep MLP high.
        uint4 qv[4];
        #pragma unroll
        for (int c = 0; c < 4; ++c) if (pr[c]) qv[c] = __ldg(gp[c]);
        unsigned u0[4], u1[4];
        #pragma unroll
        for (int c = 0; c < 4; ++c) {
            if (!pr[c]) {
                u0[c] = __ldg(tbl + av[c]);
                u1[c] = __ldg(tbl + bv[c]);
            }
        }

        float2 f[8];
        #pragma unroll
        for (int c = 0; c < 4; ++c) {
            if (pr[c]) {
                f[c]     = h2f(comp4(qv[c], s0[c]));
                f[4 + c] = h2f(comp4(qv[c], s1[c]));
            } else {
                f[c]     = h2f(u0[c]);
                f[4 + c] = h2f(u1[c]);
            }
        }

        // Trilinear blend (z fastest among the 4 combos, x split at f[4..7]).
        const float wx1 = fx, wx0 = 1.0f - fx;
        const float wy1 = fy, wy0 = 1.0f - fy;
        const float wz1 = fz, wz0 = 1.0f - fz;
        const float wxy00 = wx0 * wy0, wxy01 = wx0 * wy1;
        const float wxy10 = wx1 * wy0, wxy11 = wx1 * wy1;
        float w[8];
        w[0] = wxy00 * wz0; w[1] = wxy00 * wz1;
        w[2] = wxy01 * wz0; w[3] = wxy01 * wz1;
        w[4] = wxy10 * wz0; w[5] = wxy10 * wz1;
        w[6] = wxy11 * wz0; w[7] = wxy11 * wz1;

        float r0 = w[0] * f[0].x;
        float r1 = w[0] * f[0].y;
        #pragma unroll
        for (int j = 1; j < 8; ++j) {
            r0 = fmaf(w[j], f[j].x, r0);
            r1 = fmaf(w[j], f[j].y, r1);
        }

        sbuf[tid * 33 + 2 * l + 0] = r0;
        sbuf[tid * 33 + 2 * l + 1] = r1;
    }

    __syncthreads();

    // Coalesced copy-out; streaming stores keep tables resident in L2.
    const int nvalid = min(BLOCK_T, n - p0);
    float* __restrict__ ob = out + (size_t)p0 * 32;
    const int total = nvalid * 32;
    #pragma unroll 4
    for (int k = tid; k < total; k += BLOCK_T) {
        __stcs(ob + k, sbuf[(k >> 5) * 33 + (k & 31)]);
    }
}

extern "C" void kernel_launch(void* const* d_in, const int* in_sizes, int n_in,
                              void* d_out, int out_size)
{
    const int n = out_size / (L_LEVELS * 2);   // out is [N, 32] float32

    const float* x   = (const float*)d_in[0];
    const float* tbl = (const float*)d_in[1];
    if (n_in >= 2 && in_sizes[0] != n * 3) {
        x   = (const float*)d_in[1];
        tbl = (const float*)d_in[0];
    }

    LevelParams lp;
    const double B = pow(2.0, 7.0 / 15.0);     // log2(2048/16)/15
    int off = 0;
    for (int l = 0; l < L_LEVELS; ++l) {
        const double s = 16.0 * pow(B, (double)l) - 1.0;
        lp.scale[l] = (float)s;
        lp.res[l]   = (int)ceil(s) + 1;
        if (l < NUM_DENSE) {
            lp.doff[l] = off;
            off += lp.res[l] * lp.res[l] * lp.res[l];
        }
    }
    const int total04 = lp.doff[5];            // 330,940 (levels 0-4)
    const int total5  = off - lp.doff[5];      // 531,441 (level 5, res=81)

    // Prologues (same stream; deterministic functions of inputs).
    const int htot = NUM_HASH * (int)HASHMAP_SZ;
    build_hash_kernel<<<(htot + 255) / 256, 256>>>(tbl);
    build_dense_kernel<<<(total04 + 255) / 256, 256>>>(tbl, lp, total04);
    build_dense5_kernel<<<(total5 + 255) / 256, 256>>>(
        tbl, lp.res[5], lp.doff[5], total5);

    const int grid = (n + BLOCK_T - 1) / BLOCK_T;
    hashgrid_kernel<<<grid, BLOCK_T>>>(x, (float*)d_out, n, lp);
}